// round 17
// baseline (speedup 1.0000x reference)
#include <cuda_runtime.h>
#include <cuda_fp16.h>
#include <cstdint>

#define HIDDEN 1024
#define HEADS 16
#define HDIM 64
#define BATCH 2
#define SEQ 2048
#define ROWS (BATCH*SEQ)          // 4096
#define BH (BATCH*HEADS)          // 32
#define NEGV -1.0e9f
#define PADK 72                   // padded smem row stride (halves)
#define PADF 68                   // padded fp32 stage row stride (floats)

// ---------------- scratch (allocation-free rule) ----------------
__device__ __half g_wth[4*HIDDEN*HIDDEN];   // W^T [w][n][k] (fp16-rounded)
__device__ __half g_xh[ROWS*HIDDEN];        // x fp16
__device__ __half g_qh[BH*SEQ*HDIM];        // Q pre-scaled by 0.125
__device__ __half g_kh[BH*SEQ*HDIM];
__device__ __half g_vh[BH*SEQ*HDIM];        // V [bh][s][d] (used directly via ldsm.trans)
__device__ __half g_ctxh[ROWS*HIDDEN];
__device__ float g_y[ROWS*HIDDEN];
__device__ uint32_t g_mbits[BATCH*SEQ*(SEQ/32)];  // bit-packed mask, 1 MB

#define SMEM_P  73728   // projections: 2 stages x (A+B) 128 x PADK halves
#define SMEM_F  90112   // attn: Q,K,V tiles (55296) + fp32 stage 128 x PADF (34816)

// ---------------- helpers ----------------
__device__ __forceinline__ uint32_t smem_u32(const void* p) {
    uint32_t a;
    asm("{ .reg .u64 t; cvta.to.shared.u64 t, %1; cvt.u32.u64 %0, t; }" : "=r"(a) : "l"(p));
    return a;
}
__device__ __forceinline__ void ldsm4(uint32_t* r, const __half* p) {
    uint32_t a = smem_u32(p);
    asm volatile("ldmatrix.sync.aligned.m8n8.x4.shared.b16 {%0,%1,%2,%3}, [%4];"
        : "=r"(r[0]), "=r"(r[1]), "=r"(r[2]), "=r"(r[3]) : "r"(a));
}
// transposed ldmatrix: feeds col-major B fragments from a row-major [k][n] tile
__device__ __forceinline__ void ldsm4t(uint32_t* r, const __half* p) {
    uint32_t a = smem_u32(p);
    asm volatile("ldmatrix.sync.aligned.m8n8.x4.trans.shared.b16 {%0,%1,%2,%3}, [%4];"
        : "=r"(r[0]), "=r"(r[1]), "=r"(r[2]), "=r"(r[3]) : "r"(a));
}
__device__ __forceinline__ void mma16816(float* c, const uint32_t* a, const uint32_t* b) {
    asm volatile(
        "mma.sync.aligned.m16n8k16.row.col.f32.f16.f16.f32 "
        "{%0,%1,%2,%3}, {%4,%5,%6,%7}, {%8,%9}, {%0,%1,%2,%3};\n"
        : "+f"(c[0]), "+f"(c[1]), "+f"(c[2]), "+f"(c[3])
        : "r"(a[0]), "r"(a[1]), "r"(a[2]), "r"(a[3]), "r"(b[0]), "r"(b[1]));
}
__device__ __forceinline__ uint32_t packh2(float a, float b) {
    __half2 h = __halves2half2(__float2half_rn(a), __float2half_rn(b));
    return *(uint32_t*)&h;
}
__device__ __forceinline__ void stcs4(float* p, float4 v) {
    asm volatile("st.global.cs.v4.f32 [%0], {%1,%2,%3,%4};"
        :: "l"(p), "f"(v.x), "f"(v.y), "f"(v.z), "f"(v.w) : "memory");
}
__device__ __forceinline__ void cp16(__half* d, const __half* s) {
    uint32_t da = smem_u32(d);
    asm volatile("cp.async.cg.shared.global [%0], [%1], 16;" :: "r"(da), "l"(s));
}
#define CP_COMMIT() asm volatile("cp.async.commit_group;" ::: "memory")
#define CP_WAIT0()  asm volatile("cp.async.wait_group 0;" ::: "memory")
#define CP_WAIT1()  asm volatile("cp.async.wait_group 1;" ::: "memory")

// load [128 x 64] / [64 x 64] half tiles (row-major, stride lda) into padded smem
__device__ __forceinline__ void ldtile128(__half* dst, const __half* src, int lda, int tid) {
#pragma unroll
    for (int it = 0; it < 4; it++) {
        int idx = it * 256 + tid;
        int r = idx >> 3, j = idx & 7;
        *(uint4*)(dst + r * PADK + j * 8) = *(const uint4*)(src + (size_t)r * lda + j * 8);
    }
}
__device__ __forceinline__ void ldtile128a(__half* dst, const __half* src, int lda, int tid) {
#pragma unroll
    for (int it = 0; it < 4; it++) {
        int idx = it * 256 + tid;
        int r = idx >> 3, j = idx & 7;
        cp16(dst + r * PADK + j * 8, src + (size_t)r * lda + j * 8);
    }
}
__device__ __forceinline__ void ldtile64(__half* dst, const __half* src, int lda, int tid) {
#pragma unroll
    for (int it = 0; it < 2; it++) {
        int idx = it * 256 + tid;
        int r = idx >> 3, j = idx & 7;
        *(uint4*)(dst + r * PADK + j * 8) = *(const uint4*)(src + (size_t)r * lda + j * 8);
    }
}

// ldmatrix lane addressing
#define A_ADDR(Base, rowbase, kbase) \
    ((Base) + ((rowbase) + (lane & 15)) * PADK + (kbase) + ((lane >> 4) * 8))
#define B_ADDR(Base, nbase, kbase) \
    ((Base) + ((nbase) + ((lane >> 4) * 8) + (lane & 7)) * PADK + (kbase) + (((lane >> 3) & 1) * 8))
// trans B addressing: row = k (reduction), col = n; for row-major [k][n] tiles
#define BT_ADDR(Base, kbase, nbase) \
    ((Base) + ((kbase) + (lane & 7) + (((lane >> 3) & 1) * 8)) * PADK + (nbase) + ((lane >> 4) * 8))

// 128x128 GEMM step, single pass (pure fp16 inputs)
__device__ __forceinline__ void mma_k16x8_1(
    const __half* Ah, const __half* Bh,
    int lane, int wm, int wn, int kk, float (*c)[8][4])
{
    uint32_t ah[2][4];
#pragma unroll
    for (int mi = 0; mi < 2; mi++)
        ldsm4(ah[mi], A_ADDR(Ah, wm*32 + mi*16, kk*16));
#pragma unroll
    for (int nj = 0; nj < 4; nj++) {
        uint32_t bh4[4];
        ldsm4(bh4, B_ADDR(Bh, wn*64 + nj*16, kk*16));
#pragma unroll
        for (int mi = 0; mi < 2; mi++) {
            mma16816(c[mi][2*nj],   ah[mi], bh4);
            mma16816(c[mi][2*nj+1], ah[mi], bh4 + 2);
        }
    }
}

// ---------------------------------------------------------------------------
// Merged prep: z<4 weight transpose+round; z=4..7 x fp16; z=8 mask bit-pack.
// ---------------------------------------------------------------------------
__global__ __launch_bounds__(256) void prep_kernel(
    const float* __restrict__ Wq, const float* __restrict__ Wk,
    const float* __restrict__ Wv, const float* __restrict__ Wo,
    const float* __restrict__ x,  const int* __restrict__ am)
{
    const int z = blockIdx.z;
    const int tid = threadIdx.x;
    if (z < 4) {
        __shared__ float t[32][33];
        const float* W = (z == 0) ? Wq : (z == 1) ? Wk : (z == 2) ? Wv : Wo;
        const int n0 = blockIdx.x * 32, k0 = blockIdx.y * 32;
        {
            int kr = tid >> 3, nc = (tid & 7) * 4;
            float4 a = *(const float4*)(W + (size_t)(k0 + kr) * HIDDEN + n0 + nc);
            t[kr][nc] = a.x; t[kr][nc+1] = a.y; t[kr][nc+2] = a.z; t[kr][nc+3] = a.w;
        }
        __syncthreads();
        {
            int nr = tid >> 3, kc = (tid & 7) * 4;
            uint32_t h2[2];
            h2[0] = packh2(t[kc][nr],   t[kc+1][nr]);
            h2[1] = packh2(t[kc+2][nr], t[kc+3][nr]);
            size_t idx = (size_t)z * HIDDEN * HIDDEN + (size_t)(n0 + nr) * HIDDEN + k0 + kc;
            *(uint2*)(g_wth + idx) = *(uint2*)h2;
        }
    } else if (z < 8) {
        int blk = (z - 4) * 1024 + blockIdx.y * 32 + blockIdx.x;
        int i = blk * 256 + tid;   // float4 index, 1048576 total
        float4 a = ((const float4*)x)[i];
        uint32_t h2[2];
        h2[0] = packh2(a.x, a.y);
        h2[1] = packh2(a.z, a.w);
        ((uint2*)g_xh)[i] = *(uint2*)h2;
    } else {
        int blk = blockIdx.y * 32 + blockIdx.x;       // 0..1023
        int wi = blk * 256 + tid;                      // word index, 262144 total
        int row = wi >> 6, wslot = wi & 63;            // row over B*S, 64 words/row
        const int4* p = (const int4*)(am + (size_t)row * SEQ + wslot * 32);
        uint32_t bits = 0;
#pragma unroll
        for (int q = 0; q < 8; q++) {
            int4 m = p[q];
            bits |= (m.x ? 1u : 0u) << (q*4 + 0);
            bits |= (m.y ? 1u : 0u) << (q*4 + 1);
            bits |= (m.z ? 1u : 0u) << (q*4 + 2);
            bits |= (m.w ? 1u : 0u) << (q*4 + 3);
        }
        g_mbits[wi] = bits;
    }
}

// ---------------------------------------------------------------------------
// Q/K/V projection (HMMA, 1-pass, 2-stage cp.async): z selects W/bias/output.
// ---------------------------------------------------------------------------
__global__ __launch_bounds__(256, 2) void qkv_hmma(
    const float* __restrict__ bq, const float* __restrict__ bk,
    const float* __restrict__ bv)
{
    extern __shared__ char smraw[];
    __half* st0 = (__half*)smraw;
#define PSTG(s)  (st0 + (s) * 2 * 128 * PADK)
    const int tid = threadIdx.x, lane = tid & 31, w = tid >> 5;
    const int wm = w >> 1, wn = w & 1;
    const int z = blockIdx.z;
    const int m0 = blockIdx.y * 128, n0 = blockIdx.x * 128;

    const __half* wth = g_wth + (size_t)z * HIDDEN * HIDDEN;

    float c[2][8][4];
#pragma unroll
    for (int i = 0; i < 2; i++)
#pragma unroll
        for (int j = 0; j < 8; j++)
#pragma unroll
            for (int k = 0; k < 4; k++) c[i][j][k] = 0.f;

    ldtile128a(PSTG(0),            g_xh + (size_t)m0 * HIDDEN, HIDDEN, tid);
    ldtile128a(PSTG(0) + 128*PADK, wth + (size_t)n0 * HIDDEN, HIDDEN, tid);
    CP_COMMIT();

    for (int it = 0; it < 16; it++) {
        const int cur = it & 1;
        if (it + 1 < 16) {
            const int k1 = (it + 1) * 64;
            ldtile128a(PSTG(cur^1),            g_xh + (size_t)m0 * HIDDEN + k1, HIDDEN, tid);
            ldtile128a(PSTG(cur^1) + 128*PADK, wth + (size_t)n0 * HIDDEN + k1, HIDDEN, tid);
            CP_COMMIT();
        }
        if (it + 1 < 16) { CP_WAIT1(); } else { CP_WAIT0(); }
        __syncthreads();
        __half* sAh = PSTG(cur);
        __half* sBh = sAh + 128*PADK;
#pragma unroll
        for (int kk = 0; kk < 4; kk++)
            mma_k16x8_1(sAh, sBh, lane, wm, wn, kk, c);
        __syncthreads();
    }

    const int gid = lane >> 2, tig = lane & 3;
    const float* bias = (z == 0) ? bq : (z == 1) ? bk : bv;
    __half* outp = (z == 0) ? g_qh : (z == 1) ? g_kh : g_vh;
    const float osc = (z == 0) ? 0.125f : 1.0f;   // fold score scale into Q (exact: pow2)
#pragma unroll
    for (int mi = 0; mi < 2; mi++)
#pragma unroll
    for (int hf = 0; hf < 2; hf++) {
        int row = m0 + wm*32 + mi*16 + hf*8 + gid;
        int bb = row >> 11, s = row & (SEQ - 1);
#pragma unroll
        for (int ni = 0; ni < 8; ni++) {
            int col = n0 + wn*64 + ni*8 + tig*2;
            int h = col >> 6, d = col & 63;
            float v0 = (c[mi][ni][hf*2]     + bias[col])     * osc;
            float v1 = (c[mi][ni][hf*2 + 1] + bias[col + 1]) * osc;
            size_t o = ((size_t)(bb * HEADS + h) * SEQ + s) * HDIM + d;
            *(uint32_t*)(outp + o) = packh2(v0, v1);
        }
    }
#undef PSTG
}

// ---------------------------------------------------------------------------
// Fused attention: Q fragments hoisted; masked scores staged in warp-private
// smem, coalesced streaming writeout; P = h2exp2 fp16x2; row sums via
// ones-column MMA; V fed directly from [s][d] tiles via ldmatrix.trans.
// Grid (16 q-tiles, 32 bh), 8 warps x 16 q-rows; K/V loaded 128 rows/sync.
// ---------------------------------------------------------------------------
__global__ __launch_bounds__(256, 2) void attn_fused(float* __restrict__ sc)
{
    extern __shared__ char smraw[];
    __half* sQh = (__half*)smraw;           // 128 x PADK (Q pre-scaled)
    __half* sKh = sQh + 128*PADK;           // 128 x PADK (two 64-row k-chunks)
    __half* sVh = sKh + 128*PADK;           // 128 x PADK (V [s][d], two chunks)
    float*  sS  = (float*)(sVh + 128*PADK); // 128 x PADF fp32 stage

    const int tid = threadIdx.x, lane = tid & 31, w = tid >> 5;
    const int gid = lane >> 2, tig = lane & 3;
    const int q0 = blockIdx.x * 128, bh = blockIdx.y;
    const int b = bh >> 4, h = bh & 15;

    ldtile128(sQh, g_qh + ((size_t)bh * SEQ + q0) * HDIM, HDIM, tid);
    __syncthreads();
    uint32_t qf[4][4];
#pragma unroll
    for (int kk = 0; kk < 4; kk++)
        ldsm4(qf[kk], A_ADDR(sQh, w*16, kk*16));

    const int r0 = q0 + w*16 + gid;                 // slot-0 row; slot-1 = +8
    const uint32_t* mb0 = g_mbits + ((size_t)b * SEQ + r0) * (SEQ/32);
    const uint32_t* mb1 = mb0 + 8 * (SEQ/32);

    const uint32_t one2 = (gid == 0) ? 0x3C003C00u : 0u;
    const uint32_t b_ones[2] = { one2, one2 };
    const __half2 l2e2 = __halves2half2(__float2half(1.4426950408889634f),
                                        __float2half(1.4426950408889634f));

    float co[8][4];
    float c_ex[4];
#pragma unroll
    for (int i = 0; i < 8; i++)
#pragma unroll
        for (int j = 0; j < 4; j++) co[i][j] = 0.f;
#pragma unroll
    for (int j = 0; j < 4; j++) c_ex[j] = 0.f;

    const __half* kh = g_kh + (size_t)bh * SEQ * HDIM;
    const __half* vh = g_vh + (size_t)bh * SEQ * HDIM;
    float* swarp = sS + (w*16) * PADF;   // warp-private stage rows

    for (int ch2 = 0; ch2 < 16; ch2++) {
        const int k0 = ch2 * 128;
        __syncthreads();
        ldtile64(sKh,            kh + (size_t)k0 * HDIM,        HDIM, tid);
        ldtile64(sKh + 64*PADK,  kh + (size_t)(k0 + 64) * HDIM, HDIM, tid);
        ldtile64(sVh,            vh + (size_t)k0 * HDIM,        HDIM, tid);
        ldtile64(sVh + 64*PADK,  vh + (size_t)(k0 + 64) * HDIM, HDIM, tid);
        __syncthreads();

#pragma unroll
        for (int hf2 = 0; hf2 < 2; hf2++) {
            const __half* Kt = sKh + hf2 * 64*PADK;
            const __half* Vt = sVh + hf2 * 64*PADK;
            const int kc = k0 + hf2 * 64;

            float cs[8][4];
#pragma unroll
            for (int i = 0; i < 8; i++)
#pragma unroll
                for (int j = 0; j < 4; j++) cs[i][j] = 0.f;
#pragma unroll
            for (int kk = 0; kk < 4; kk++) {
#pragma unroll
                for (int nj = 0; nj < 4; nj++) {
                    uint32_t b4[4];
                    ldsm4(b4, B_ADDR(Kt, nj*16, kk*16));
                    mma16816(cs[2*nj],   qf[kk], b4);
                    mma16816(cs[2*nj+1], qf[kk], b4 + 2);
                }
            }

            uint2 w0 = *(const uint2*)(mb0 + (kc >> 5));
            uint2 w1 = *(const uint2*)(mb1 + (kc >> 5));

            __syncwarp();   // prior iteration's stage reads complete (WAR)
#pragma unroll
            for (int ni = 0; ni < 8; ni++) {
                uint32_t s0 = ((ni < 4) ? w0.x : w0.y) >> ((ni & 3)*8 + tig*2);
                uint32_t s1 = ((ni < 4) ? w1.x : w1.y) >> ((ni & 3)*8 + tig*2);
                cs[ni][0] = (s0 & 1u) ? cs[ni][0] : NEGV;
                cs[ni][1] = (s0 & 2u) ? cs[ni][1] : NEGV;
                cs[ni][2] = (s1 & 1u) ? cs[ni][2] : NEGV;
                cs[ni][3] = (s1 & 2u) ? cs[ni][3] : NEGV;
                *(float2*)(swarp + gid*PADF + ni*8 + tig*2)     = make_float2(cs[ni][0], cs[ni][1]);
                *(float2*)(swarp + (gid+8)*PADF + ni*8 + tig*2) = make_float2(cs[ni][2], cs[ni][3]);
            }
            __syncwarp();
            {
                const int lr0 = lane >> 3, c0 = (lane & 7) * 4;
#pragma unroll
                for (int j = 0; j < 4; j++) {
                    int lr = lr0 + j*4;
                    float* grow = sc + ((size_t)bh * SEQ + q0 + w*16 + lr) * SEQ + kc;
#pragma unroll
                    for (int i = 0; i < 2; i++) {
                        float4 v = *(float4*)(swarp + lr*PADF + c0 + i*32);
                        stcs4(grow + c0 + i*32, v);
                    }
                }
            }
            // exp (fp16x2) + PV (V via ldsm.trans) + ones-column sums
#pragma unroll
            for (int kk = 0; kk < 4; kk++) {
                __half2 p0 = h2exp2(__hmul2(__floats2half2_rn(cs[2*kk][0],   cs[2*kk][1]),   l2e2));
                __half2 p1 = h2exp2(__hmul2(__floats2half2_rn(cs[2*kk][2],   cs[2*kk][3]),   l2e2));
                __half2 p2 = h2exp2(__hmul2(__floats2half2_rn(cs[2*kk+1][0], cs[2*kk+1][1]), l2e2));
                __half2 p3 = h2exp2(__hmul2(__floats2half2_rn(cs[2*kk+1][2], cs[2*kk+1][3]), l2e2));
                uint32_t a[4] = { *(uint32_t*)&p0, *(uint32_t*)&p1,
                                  *(uint32_t*)&p2, *(uint32_t*)&p3 };
#pragma unroll
                for (int nj = 0; nj < 4; nj++) {
                    uint32_t b4[4];
                    ldsm4t(b4, BT_ADDR(Vt, kk*16, nj*16));
                    mma16816(co[2*nj],   a, b4);
                    mma16816(co[2*nj+1], a, b4 + 2);
                }
                mma16816(c_ex, a, b_ones);
            }
        }
    }

    float sum0 = __shfl_sync(0xffffffffu, c_ex[0], lane & 28);
    float sum1 = __shfl_sync(0xffffffffu, c_ex[2], lane & 28);
    float ri0 = 1.f / sum0, ri1 = 1.f / sum1;

    size_t ob0 = ((size_t)(b * SEQ + r0)) * HIDDEN + h * HDIM;
    size_t ob1 = ob0 + (size_t)8 * HIDDEN;
#pragma unroll
    for (int ni = 0; ni < 8; ni++) {
        int d = ni*8 + tig*2;
        *(uint32_t*)(g_ctxh + ob0 + d) = packh2(co[ni][0] * ri0, co[ni][1] * ri0);
        *(uint32_t*)(g_ctxh + ob1 + d) = packh2(co[ni][2] * ri1, co[ni][3] * ri1);
    }
}

// ---------------------------------------------------------------------------
// Out projection + residual (HMMA, 1-pass, 2-stage cp.async)
// ---------------------------------------------------------------------------
__global__ __launch_bounds__(256, 2) void proj_hmma(
    const float* __restrict__ bo, const float* __restrict__ x)
{
    extern __shared__ char smraw[];
    __half* st0 = (__half*)smraw;
#define PSTG(s)  (st0 + (s) * 2 * 128 * PADK)
    const int tid = threadIdx.x, lane = tid & 31, w = tid >> 5;
    const int wm = w >> 1, wn = w & 1;
    const int m0 = blockIdx.y * 128, n0 = blockIdx.x * 128;

    const __half* wth = g_wth + (size_t)3 * HIDDEN * HIDDEN;

    float c[2][8][4];
#pragma unroll
    for (int i = 0; i < 2; i++)
#pragma unroll
        for (int j = 0; j < 8; j++)
#pragma unroll
            for (int k = 0; k < 4; k++) c[i][j][k] = 0.f;

    ldtile128a(PSTG(0),            g_ctxh + (size_t)m0 * HIDDEN, HIDDEN, tid);
    ldtile128a(PSTG(0) + 128*PADK, wth + (size_t)n0 * HIDDEN, HIDDEN, tid);
    CP_COMMIT();

    for (int it = 0; it < 16; it++) {
        const int cur = it & 1;
        if (it + 1 < 16) {
            const int k1 = (it + 1) * 64;
            ldtile128a(PSTG(cur^1),            g_ctxh + (size_t)m0 * HIDDEN + k1, HIDDEN, tid);
            ldtile128a(PSTG(cur^1) + 128*PADK, wth + (size_t)n0 * HIDDEN + k1, HIDDEN, tid);
            CP_COMMIT();
        }
        if (it + 1 < 16) { CP_WAIT1(); } else { CP_WAIT0(); }
        __syncthreads();
        __half* sAh = PSTG(cur);
        __half* sBh = sAh + 128*PADK;
#pragma unroll
        for (int kk = 0; kk < 4; kk++)
            mma_k16x8_1(sAh, sBh, lane, wm, wn, kk, c);
        __syncthreads();
    }

    const int gid = lane >> 2, tig = lane & 3;
#pragma unroll
    for (int mi = 0; mi < 2; mi++)
#pragma unroll
    for (int hf = 0; hf < 2; hf++) {
        int row = m0 + wm*32 + mi*16 + hf*8 + gid;
#pragma unroll
        for (int ni = 0; ni < 8; ni++) {
            int col = n0 + wn*64 + ni*8 + tig*2;
            float2 xv = *(const float2*)(x + (size_t)row * HIDDEN + col);
            float2 st;
            st.x = c[mi][ni][hf*2]     + bo[col]     + xv.x;
            st.y = c[mi][ni][hf*2 + 1] + bo[col + 1] + xv.y;
            *(float2*)(g_y + (size_t)row * HIDDEN + col) = st;
        }
    }
#undef PSTG
}

// ---------------------------------------------------------------------------
// LayerNorm over last dim of g_y -> out
// ---------------------------------------------------------------------------
__global__ __launch_bounds__(256) void ln_kernel(
    const float* __restrict__ gamma, const float* __restrict__ beta,
    float* __restrict__ out)
{
    const int row = blockIdx.x;
    const int tid = threadIdx.x;
    __shared__ float red[8];
    const float4* p = (const float4*)(g_y + (size_t)row * HIDDEN);
    float4 v = p[tid];

    float s = v.x + v.y + v.z + v.w;
#pragma unroll
    for (int o = 16; o; o >>= 1) s += __shfl_xor_sync(0xffffffffu, s, o);
    if ((tid & 31) == 0) red[tid >> 5] = s;
    __syncthreads();
    if (tid < 32) {
        float t = (tid < 8) ? red[tid] : 0.f;
#pragma unroll
        for (int o = 4; o; o >>= 1) t += __shfl_xor_sync(0xffffffffu, t, o);
        if (tid == 0) red[0] = t;
    }
    __syncthreads();
    float mu = red[0] * (1.f / HIDDEN);
    __syncthreads();

    float dx = v.x - mu, dy = v.y - mu, dz = v.z - mu, dw = v.w - mu;
    float s2 = dx*dx + dy*dy + dz*dz + dw*dw;
#pragma unroll
    for (int o = 16; o; o >>= 1) s2 += __shfl_xor_sync(0xffffffffu, s2, o);
    if ((tid & 31) == 0) red[tid >> 5] = s2;
    __syncthreads();
    if (tid < 32) {
        float t = (tid < 8) ? red[tid] : 0.f;
#pragma unroll
        for (int o = 4; o; o >>= 1) t += __shfl_xor_sync(0xffffffffu, t, o);
        if (tid == 0) red[0] = t;
    }
    __syncthreads();
    float var = red[0] * (1.f / HIDDEN);
    float rs = rsqrtf(var + 1e-12f);

    float4 gg = ((const float4*)gamma)[tid];
    float4 bb = ((const float4*)beta)[tid];
    float4 o4;
    o4.x = dx * rs * gg.x + bb.x;
    o4.y = dy * rs * gg.y + bb.y;
    o4.z = dz * rs * gg.z + bb.z;
    o4.w = dw * rs * gg.w + bb.w;
    ((float4*)(out + (size_t)row * HIDDEN))[tid] = o4;
}

// ---------------------------------------------------------------------------
extern "C" void kernel_launch(void* const* d_in, const int* in_sizes, int n_in,
                              void* d_out, int out_size)
{
    const float* x  = (const float*)d_in[0];
    const int*   am = (const int*)d_in[1];
    const float* Wq = (const float*)d_in[2];  const float* bq = (const float*)d_in[3];
    const float* Wk = (const float*)d_in[4];  const float* bk = (const float*)d_in[5];
    const float* Wv = (const float*)d_in[6];  const float* bv = (const float*)d_in[7];
    const float* Wo = (const float*)d_in[8];  const float* bo = (const float*)d_in[9];
    const float* lg = (const float*)d_in[10]; const float* lb = (const float*)d_in[11];

    float* out = (float*)d_out;
    float* sc  = out + (size_t)ROWS * HIDDEN;   // scores follow `out` in the tuple

    cudaFuncSetAttribute(qkv_hmma,   cudaFuncAttributeMaxDynamicSharedMemorySize, SMEM_P);
    cudaFuncSetAttribute(attn_fused, cudaFuncAttributeMaxDynamicSharedMemorySize, SMEM_F);
    cudaFuncSetAttribute(proj_hmma,  cudaFuncAttributeMaxDynamicSharedMemorySize, SMEM_P);

    prep_kernel<<<dim3(32, 32, 9), 256>>>(Wq, Wk, Wv, Wo, x, am);
    qkv_hmma<<<dim3(8, 32, 3), 256, SMEM_P>>>(bq, bk, bv);
    attn_fused<<<dim3(16, 32), 256, SMEM_F>>>(sc);
    proj_hmma<<<dim3(8, 32), 256, SMEM_P>>>(bo, x);
    ln_kernel<<<ROWS, 256>>>(lg, lb, out);
}